// round 4
// baseline (speedup 1.0000x reference)
#include <cuda_runtime.h>
#include <cstdint>

#define BB 8
#define CC 128
#define HH 160
#define WW 512
#define DMAX 64

#define TJ_BLK 128
#define NCHUNK 4       // 4 chunks x 32 channels
#define NC4 8          // channel-quads per chunk
#define SLP 129        // float4 per sL row (128 cols + pad)
#define SRP 193        // float4 per sR row (192 cols + pad)

__device__ __forceinline__ uint32_t swzc(uint32_t col) {
    return col ^ ((col >> 3) & 0x7u);
}
__device__ __forceinline__ void ffma2(unsigned long long& d, unsigned long long a,
                                      unsigned long long b) {
    asm("fma.rn.f32x2 %0, %1, %2, %0;" : "+l"(d) : "l"(a), "l"(b));
}

__global__ __launch_bounds__(128, 2)
void cost_volume_kernel(const float* __restrict__ left,
                        const float* __restrict__ right,
                        float* __restrict__ out) {
    // element = float4 holding 4 consecutive channels' values at one column j
    __shared__ float4 sL[NC4][SLP];   // 16512 B
    __shared__ float4 sR[NC4][SRP];   // 24704 B

    const int tid = threadIdx.x;
    const int j0B = blockIdx.x * TJ_BLK;
    const int h   = blockIdx.y;
    const int b   = blockIdx.z;

    // compute map: td -> 8 disparities, tj -> 8 j's
    const int td = tid & 7;
    const int tj = tid >> 3;

    const size_t plane = (size_t)HH * WW;
    const float* Lbase = left  + ((size_t)b * CC * HH + h) * WW;
    const float* Rbase = right + ((size_t)b * CC * HH + h) * WW;

    // precomputed swizzled column indices
    uint32_t lI[8];
    #pragma unroll
    for (int jj = 0; jj < 8; jj++) lI[jj] = swzc((uint32_t)(tj * 8 + jj));
    uint32_t rI[15];
    const int rb = tj * 8 - td * 8 + 57;   // window col for s=0
    #pragma unroll
    for (int s = 0; s < 15; s++) rI[s] = swzc((uint32_t)(rb + s));

    // accumulators: f32x2 packed over channel pairs (both quad-halves fold in)
    unsigned long long acc[8][8];
    #pragma unroll
    for (int dd = 0; dd < 8; dd++)
        #pragma unroll
        for (int jj = 0; jj < 8; jj++) acc[dd][jj] = 0ull;

    for (int chunk = 0; chunk < NCHUNK; chunk++) {
        __syncthreads();   // prior compute reads done before overwrite

        // ---- load L tile: 256 items = (c4 in [0,8)) x (32 col-groups of 4) ----
        #pragma unroll
        for (int it = 0; it < 2; it++) {
            const int idx = it * 128 + tid;
            const int c4  = idx >> 5;
            const int g   = idx & 31;
            const float* p = Lbase + (size_t)(chunk * 32 + c4 * 4) * plane + j0B + g * 4;
            const float4 t0 = *reinterpret_cast<const float4*>(p);
            const float4 t1 = *reinterpret_cast<const float4*>(p + plane);
            const float4 t2 = *reinterpret_cast<const float4*>(p + 2 * plane);
            const float4 t3 = *reinterpret_cast<const float4*>(p + 3 * plane);
            sL[c4][swzc((uint32_t)(g * 4 + 0))] = make_float4(t0.x, t1.x, t2.x, t3.x);
            sL[c4][swzc((uint32_t)(g * 4 + 1))] = make_float4(t0.y, t1.y, t2.y, t3.y);
            sL[c4][swzc((uint32_t)(g * 4 + 2))] = make_float4(t0.z, t1.z, t2.z, t3.z);
            sL[c4][swzc((uint32_t)(g * 4 + 3))] = make_float4(t0.w, t1.w, t2.w, t3.w);
        }

        // ---- load R window: 384 items = (c4 in [0,8)) x (48 col-groups of 4) ----
        #pragma unroll
        for (int it = 0; it < 3; it++) {
            const int idx = it * 128 + tid;
            const int c4  = idx / 48;
            const int g   = idx - c4 * 48;
            const int gj0 = j0B - 64 + g * 4;      // global j of window col g*4
            float4 t0, t1, t2, t3;
            if (gj0 >= 0) {
                const float* p = Rbase + (size_t)(chunk * 32 + c4 * 4) * plane + gj0;
                t0 = *reinterpret_cast<const float4*>(p);
                t1 = *reinterpret_cast<const float4*>(p + plane);
                t2 = *reinterpret_cast<const float4*>(p + 2 * plane);
                t3 = *reinterpret_cast<const float4*>(p + 3 * plane);
            } else {
                t0 = make_float4(0.f, 0.f, 0.f, 0.f);  // feeds only masked j<d outputs
                t1 = t0; t2 = t0; t3 = t0;
            }
            sR[c4][swzc((uint32_t)(g * 4 + 0))] = make_float4(t0.x, t1.x, t2.x, t3.x);
            sR[c4][swzc((uint32_t)(g * 4 + 1))] = make_float4(t0.y, t1.y, t2.y, t3.y);
            sR[c4][swzc((uint32_t)(g * 4 + 2))] = make_float4(t0.z, t1.z, t2.z, t3.z);
            sR[c4][swzc((uint32_t)(g * 4 + 3))] = make_float4(t0.w, t1.w, t2.w, t3.w);
        }

        __syncthreads();

        // ---- compute: 8 channel-quads x (8 d x 8 j), LDS.128 operands ----
        #pragma unroll
        for (int c4 = 0; c4 < NC4; c4++) {
            ulonglong2 lv[8];
            #pragma unroll
            for (int jj = 0; jj < 8; jj++)
                lv[jj] = *reinterpret_cast<const ulonglong2*>(&sL[c4][lI[jj]]);

            ulonglong2 rv[15];
            // phase A: dd 0..3 uses rv[4..14]
            #pragma unroll
            for (int s = 4; s < 15; s++)
                rv[s] = *reinterpret_cast<const ulonglong2*>(&sR[c4][rI[s]]);
            #pragma unroll
            for (int dd = 0; dd < 4; dd++)
                #pragma unroll
                for (int jj = 0; jj < 8; jj++) {
                    ffma2(acc[dd][jj], lv[jj].x, rv[jj - dd + 7].x);
                    ffma2(acc[dd][jj], lv[jj].y, rv[jj - dd + 7].y);
                }
            // phase B: dd 4..7 uses rv[0..10]
            #pragma unroll
            for (int s = 0; s < 4; s++)
                rv[s] = *reinterpret_cast<const ulonglong2*>(&sR[c4][rI[s]]);
            #pragma unroll
            for (int dd = 4; dd < 8; dd++)
                #pragma unroll
                for (int jj = 0; jj < 8; jj++) {
                    ffma2(acc[dd][jj], lv[jj].x, rv[jj - dd + 7].x);
                    ffma2(acc[dd][jj], lv[jj].y, rv[jj - dd + 7].y);
                }
        }
    }

    // ---- epilogue: reduce pair, scale 1/C, mask j<d, float4 stores ----
    const float inv = 1.0f / (float)CC;
    float* obase = out + ((size_t)b * DMAX * HH + h) * WW;
    #pragma unroll
    for (int dd = 0; dd < 8; dd++) {
        const int d = td * 8 + dd;
        float* orow = obase + (size_t)d * plane + j0B + tj * 8;
        #pragma unroll
        for (int q = 0; q < 2; q++) {
            float vals[4];
            #pragma unroll
            for (int i = 0; i < 4; i++) {
                const int jj = q * 4 + i;
                union { unsigned long long u; float2 f2; } cv;
                cv.u = acc[dd][jj];
                const float f = (cv.f2.x + cv.f2.y) * inv;
                const int j = j0B + tj * 8 + jj;
                vals[i] = (j >= d) ? f : 0.0f;
            }
            float4 o;
            o.x = vals[0]; o.y = vals[1]; o.z = vals[2]; o.w = vals[3];
            *reinterpret_cast<float4*>(orow + q * 4) = o;
        }
    }
}

extern "C" void kernel_launch(void* const* d_in, const int* in_sizes, int n_in,
                              void* d_out, int out_size) {
    const float* left  = (const float*)d_in[0];
    const float* right = (const float*)d_in[1];
    float* out = (float*)d_out;

    dim3 grid(WW / TJ_BLK, HH, BB);
    cost_volume_kernel<<<grid, 128>>>(left, right, out);
}

// round 6
// speedup vs baseline: 1.1454x; 1.1454x over previous
#include <cuda_runtime.h>
#include <cstdint>

#define BB 8
#define CC 128
#define HH 160
#define WW 512
#define DMAX 64
#define TJ 128
#define THREADS 256

#define SJ 200          // A row stride (floats): window 192 + pad -> 8c bank rotation
#define SJB 136         // B row stride (floats): 128 + pad -> 8c bank rotation
#define ASZ (32 * SJ)   // 6400 floats per A chunk buffer
#define BSZ (32 * SJB)  // 4352 floats per B chunk buffer
#define A0 0
#define A1 ASZ
#define B0 (2 * ASZ)
#define B1 (2 * ASZ + BSZ)
#define SM_FLOATS (2 * ASZ + 2 * BSZ)     // 21504 floats = 86016 B
#define SOUT_STRIDE 132

__device__ __forceinline__ float to_tf32f(float f) {
    uint32_t r;
    asm("cvt.rna.tf32.f32 %0, %1;" : "=r"(r) : "f"(f));
    return __uint_as_float(r);
}
__device__ __forceinline__ void mma_tf32(float* d, const uint32_t* a, const uint32_t* b) {
    asm volatile(
        "mma.sync.aligned.m16n8k8.row.col.f32.tf32.tf32.f32 "
        "{%0,%1,%2,%3}, {%4,%5,%6,%7}, {%8,%9}, {%0,%1,%2,%3};"
        : "+f"(d[0]), "+f"(d[1]), "+f"(d[2]), "+f"(d[3])
        : "r"(a[0]), "r"(a[1]), "r"(a[2]), "r"(a[3]), "r"(b[0]), "r"(b[1]));
}

__global__ __launch_bounds__(THREADS)
void cost_volume_kernel(const float* __restrict__ left,
                        const float* __restrict__ right,
                        float* __restrict__ out) {
    extern __shared__ float sm[];

    const int tid = threadIdx.x;
    const int wid = tid >> 5;
    const int lid = tid & 31;
    const int gid = lid >> 2;       // group id 0..7
    const int tig = lid & 3;        // thread in group 0..3
    const int j0  = blockIdx.x * TJ;
    const int h   = blockIdx.y;
    const int b   = blockIdx.z;

    const size_t plane = (size_t)HH * WW;
    const float* Lbase = left  + ((size_t)b * CC * HH + h) * WW;
    const float* Rbase = right + ((size_t)b * CC * HH + h) * WW;

    // warp tile: G0 (warps 0-3): k rows [wid*32, +32), jj [0,64)
    //            G1 (warps 4-7): k rows [64+(wid-4)*32, +32), jj [64,128)
    const int g   = wid >> 2;
    const int kw  = g ? (64 + (wid - 4) * 32) : (wid * 32);
    const int jjb = g * 64;

    // staging map: c = channel-in-chunk (32), qb = quad slot
    const int sc = tid >> 3;
    const int qb = tid & 7;

    float acc[2][8][4];
    #pragma unroll
    for (int mt = 0; mt < 2; mt++)
        #pragma unroll
        for (int nt = 0; nt < 8; nt++)
            #pragma unroll
            for (int r = 0; r < 4; r++) acc[mt][nt][r] = 0.0f;

    for (int chunk = 0; chunk < 4; chunk++) {
        const int buf = chunk & 1;
        __syncthreads();   // prior compute on this buffer done

        // ---- stage A: R window rows, natural [c][jw] layout, jw in [0,192) ----
        {
            const int ch = chunk * 32 + sc;
            const float* Rrow = Rbase + (size_t)ch * plane;
            float* Ab = sm + (buf ? A1 : A0) + sc * SJ;
            #pragma unroll
            for (int i = 0; i < 6; i++) {
                const int q = qb + 8 * i;            // 0..47
                const int gj = j0 - 64 + 4 * q;
                float4 t = make_float4(0.f, 0.f, 0.f, 0.f);
                if (gj >= 0) t = *reinterpret_cast<const float4*>(Rrow + gj);
                float4 w;
                w.x = to_tf32f(t.x); w.y = to_tf32f(t.y);
                w.z = to_tf32f(t.z); w.w = to_tf32f(t.w);
                *reinterpret_cast<float4*>(Ab + 4 * q) = w;
            }
            // ---- stage B: L tile, natural [c][jj] layout, jj in [0,128) ----
            const float* Lrow = Lbase + (size_t)ch * plane + j0;
            float* Bb = sm + (buf ? B1 : B0) + sc * SJB;
            #pragma unroll
            for (int i = 0; i < 4; i++) {
                const int q = qb + 8 * i;            // 0..31
                const float4 t = *reinterpret_cast<const float4*>(Lrow + 4 * q);
                float4 w;
                w.x = to_tf32f(t.x); w.y = to_tf32f(t.y);
                w.z = to_tf32f(t.z); w.w = to_tf32f(t.w);
                *reinterpret_cast<float4*>(Bb + 4 * q) = w;
            }
        }
        __syncthreads();

        // ---- compute: 4 k8 steps of mma.sync tf32 ----
        const float* A = sm + (buf ? A1 : A0);
        const float* B = sm + (buf ? B1 : B0);
        #pragma unroll
        for (int s = 0; s < 4; s++) {
            const float* Ac = A + (s * 8 + tig) * SJ;
            const float* Bc = B + (s * 8 + tig) * SJB;
            uint32_t af[2][4];
            #pragma unroll
            for (int mt = 0; mt < 2; mt++) {
                const int base = kw + mt * 16 + gid;
                af[mt][0] = __float_as_uint(Ac[base]);
                af[mt][1] = __float_as_uint(Ac[base + 8]);
                af[mt][2] = __float_as_uint(Ac[4 * SJ + base]);
                af[mt][3] = __float_as_uint(Ac[4 * SJ + base + 8]);
            }
            uint32_t bf[8][2];
            #pragma unroll
            for (int nt = 0; nt < 8; nt++) {
                const int jl = jjb + nt * 8 + gid;
                bf[nt][0] = __float_as_uint(Bc[jl]);
                bf[nt][1] = __float_as_uint(Bc[4 * SJB + jl]);
            }
            #pragma unroll
            for (int mt = 0; mt < 2; mt++)
                #pragma unroll
                for (int nt = 0; nt < 8; nt++)
                    mma_tf32(acc[mt][nt], af[mt], bf[nt]);
        }
    }

    // ---- epilogue: band extract into smem (aliases A buffers), then store ----
    __syncthreads();   // all compute done before sOut overwrites A0/A1
    {
        const float inv = 1.0f / (float)CC;
        float* sOut = sm;   // 64 x SOUT_STRIDE floats = 33792 B (fits in A0+A1)
        #pragma unroll
        for (int mt = 0; mt < 2; mt++) {
            const int k0t = kw + mt * 16 + gid;
            #pragma unroll
            for (int nt = 0; nt < 8; nt++) {
                const int jj0t = jjb + nt * 8 + 2 * tig;
                #pragma unroll
                for (int r = 0; r < 4; r++) {
                    const int kk = k0t + ((r >= 2) ? 8 : 0);
                    const int jx = jj0t + (r & 1);
                    const int d  = jx + 64 - kk;
                    if (d >= 0 && d < 64) {
                        const int j = j0 + jx;
                        const float v = (j >= d) ? acc[mt][nt][r] * inv : 0.0f;
                        sOut[d * SOUT_STRIDE + jx] = v;
                    }
                }
            }
        }
    }
    __syncthreads();
    {
        const float* sOut = sm;
        float* obase = out + ((size_t)b * DMAX * HH + h) * WW + j0;
        #pragma unroll
        for (int it = 0; it < 8; it++) {
            const int idx = it * THREADS + tid;      // 0..2047 float4 slots
            const int d  = idx >> 5;
            const int qq = idx & 31;
            const float4 v = *reinterpret_cast<const float4*>(sOut + d * SOUT_STRIDE + 4 * qq);
            *reinterpret_cast<float4*>(obase + (size_t)d * plane + 4 * qq) = v;
        }
    }
}

extern "C" void kernel_launch(void* const* d_in, const int* in_sizes, int n_in,
                              void* d_out, int out_size) {
    const float* left  = (const float*)d_in[0];
    const float* right = (const float*)d_in[1];
    float* out = (float*)d_out;

    cudaFuncSetAttribute(cost_volume_kernel,
                         cudaFuncAttributeMaxDynamicSharedMemorySize,
                         SM_FLOATS * (int)sizeof(float));

    dim3 grid(WW / TJ, HH, BB);
    cost_volume_kernel<<<grid, THREADS, SM_FLOATS * sizeof(float)>>>(left, right, out);
}

// round 7
// speedup vs baseline: 1.8538x; 1.6185x over previous
#include <cuda_runtime.h>
#include <cuda_fp16.h>
#include <cstdint>

#define BB 8
#define CC 128
#define HH 160
#define WW 512
#define DMAX 64
#define TJ 128
#define THREADS 256

#define SJ2 200           // sA row stride in half2 units (192 + pad), ≡8 mod 32
#define SJB2 136          // sB row stride in half2 units (128 + pad), ≡8 mod 32
#define ASZ (16 * SJ2)    // 3200 half2 per A buffer
#define BSZ (16 * SJB2)   // 2176 half2 per B buffer
#define A0o 0
#define A1o ASZ
#define B0o (2 * ASZ)
#define B1o (2 * ASZ + BSZ)
#define SM_UINTS (2 * ASZ + 2 * BSZ)   // 10752 uints = 43008 B
#define SOUT_STRIDE 132                // 64*132*4 = 33792 B fits in smem alias

__device__ __forceinline__ void mma_f16(float* d, const uint32_t* a, const uint32_t* b) {
    asm volatile(
        "mma.sync.aligned.m16n8k16.row.col.f32.f16.f16.f32 "
        "{%0,%1,%2,%3}, {%4,%5,%6,%7}, {%8,%9}, {%0,%1,%2,%3};"
        : "+f"(d[0]), "+f"(d[1]), "+f"(d[2]), "+f"(d[3])
        : "r"(a[0]), "r"(a[1]), "r"(a[2]), "r"(a[3]), "r"(b[0]), "r"(b[1]));
}
__device__ __forceinline__ uint32_t pack2(float lo, float hi) {
    const __half2 h = __floats2half2_rn(lo, hi);   // .x = lo
    return *reinterpret_cast<const uint32_t*>(&h);
}

__global__ __launch_bounds__(THREADS, 2)
void cost_volume_kernel(const float* __restrict__ left,
                        const float* __restrict__ right,
                        float* __restrict__ out) {
    __shared__ uint32_t sm[SM_UINTS];

    const int tid = threadIdx.x;
    const int wid = tid >> 5;
    const int lid = tid & 31;
    const int gid = lid >> 2;       // 0..7
    const int tig = lid & 3;        // 0..3
    const int j0  = blockIdx.x * TJ;
    const int h   = blockIdx.y;
    const int b   = blockIdx.z;

    const size_t plane = (size_t)HH * WW;
    const float* Lbase = left  + ((size_t)b * CC * HH + h) * WW;
    const float* Rbase = right + ((size_t)b * CC * HH + h) * WW;

    // warp tile: G0 (w0-3): k in [w*32, +32), jj [0,64); G1 (w4-7): k in [64+(w-4)*32,+32), jj [64,128)
    const int g   = wid >> 2;
    const int kw  = g ? (64 + (wid - 4) * 32) : (wid * 32);
    const int jjb = g * 64;

    // staging map: warp owns channel-pairs {2w, 2w+1}; lane: sub selects pair, gl = position group
    const int sub = lid >> 4;
    const int c2s = 2 * wid + sub;          // 0..15
    const int gl  = lid & 15;

    float acc[2][8][4];
    #pragma unroll
    for (int mt = 0; mt < 2; mt++)
        #pragma unroll
        for (int nt = 0; nt < 8; nt++)
            #pragma unroll
            for (int r = 0; r < 4; r++) acc[mt][nt][r] = 0.0f;

    for (int chunk = 0; chunk < 4; chunk++) {
        const int buf = chunk & 1;
        __syncthreads();   // prior compute on this buffer finished

        // ---- stage A: R window rows [c2][k 0..191] as half2 (ch even=lo, odd=hi) ----
        {
            const int ch = chunk * 32 + 2 * c2s;
            const float* R0 = Rbase + (size_t)ch * plane;
            const float* R1 = R0 + plane;
            uint32_t* Ab = sm + (buf ? A1o : A0o) + c2s * SJ2;
            #pragma unroll
            for (int i = 0; i < 3; i++) {
                const int q  = i * 16 + gl;          // 0..47
                const int gj = j0 - 64 + 4 * q;
                float4 e = make_float4(0.f, 0.f, 0.f, 0.f), o = e;
                if (gj >= 0) {
                    e = *reinterpret_cast<const float4*>(R0 + gj);
                    o = *reinterpret_cast<const float4*>(R1 + gj);
                }
                uint4 w;
                w.x = pack2(e.x, o.x); w.y = pack2(e.y, o.y);
                w.z = pack2(e.z, o.z); w.w = pack2(e.w, o.w);
                *reinterpret_cast<uint4*>(Ab + 4 * q) = w;
            }
            // ---- stage B: L tile [c2][jj 0..127] ----
            const float* L0 = Lbase + (size_t)ch * plane + j0;
            const float* L1 = L0 + plane;
            uint32_t* Bb = sm + (buf ? B1o : B0o) + c2s * SJB2;
            #pragma unroll
            for (int i = 0; i < 2; i++) {
                const int q = i * 16 + gl;           // 0..31
                const float4 e = *reinterpret_cast<const float4*>(L0 + 4 * q);
                const float4 o = *reinterpret_cast<const float4*>(L1 + 4 * q);
                uint4 w;
                w.x = pack2(e.x, o.x); w.y = pack2(e.y, o.y);
                w.z = pack2(e.z, o.z); w.w = pack2(e.w, o.w);
                *reinterpret_cast<uint4*>(Bb + 4 * q) = w;
            }
        }
        __syncthreads();

        // ---- compute: 2 k16 steps ----
        const uint32_t* Abase = sm + (buf ? A1o : A0o);
        const uint32_t* Bbase = sm + (buf ? B1o : B0o);
        #pragma unroll
        for (int s = 0; s < 2; s++) {
            const uint32_t* As  = Abase + (s * 8 + tig) * SJ2;
            const uint32_t* As4 = As + 4 * SJ2;
            const uint32_t* Bs  = Bbase + (s * 8 + tig) * SJB2;
            const uint32_t* Bs4 = Bs + 4 * SJB2;

            uint32_t af[2][4];
            #pragma unroll
            for (int mt = 0; mt < 2; mt++) {
                const int p = kw + mt * 16 + gid;
                af[mt][0] = As[p];       af[mt][1] = As[p + 8];
                af[mt][2] = As4[p];      af[mt][3] = As4[p + 8];
            }
            uint32_t bf[8][2];
            #pragma unroll
            for (int nt = 0; nt < 8; nt++) {
                const int jl = jjb + nt * 8 + gid;
                bf[nt][0] = Bs[jl];      bf[nt][1] = Bs4[jl];
            }
            #pragma unroll
            for (int mt = 0; mt < 2; mt++)
                #pragma unroll
                for (int nt = 0; nt < 8; nt++)
                    mma_f16(acc[mt][nt], af[mt], bf[nt]);
        }
    }

    // ---- epilogue: band extract -> smem (aliases buffers) -> coalesced store ----
    __syncthreads();
    {
        const float inv = 1.0f / (float)CC;
        float* sOut = reinterpret_cast<float*>(sm);
        #pragma unroll
        for (int mt = 0; mt < 2; mt++) {
            const int k0t = kw + mt * 16 + gid;
            #pragma unroll
            for (int nt = 0; nt < 8; nt++) {
                const int jj0t = jjb + nt * 8 + 2 * tig;
                #pragma unroll
                for (int r = 0; r < 4; r++) {
                    const int kk = k0t + ((r >= 2) ? 8 : 0);
                    const int jx = jj0t + (r & 1);
                    const int d  = jx + 64 - kk;
                    if (d >= 0 && d < 64) {
                        const int j = j0 + jx;
                        sOut[d * SOUT_STRIDE + jx] = (j >= d) ? acc[mt][nt][r] * inv : 0.0f;
                    }
                }
            }
        }
    }
    __syncthreads();
    {
        const float* sOut = reinterpret_cast<const float*>(sm);
        float* obase = out + ((size_t)b * DMAX * HH + h) * WW + j0;
        #pragma unroll
        for (int it = 0; it < 8; it++) {
            const int idx = it * THREADS + tid;   // 2048 float4 slots
            const int d  = idx >> 5;
            const int qq = idx & 31;
            const float4 v = *reinterpret_cast<const float4*>(sOut + d * SOUT_STRIDE + 4 * qq);
            *reinterpret_cast<float4*>(obase + (size_t)d * plane + 4 * qq) = v;
        }
    }
}

extern "C" void kernel_launch(void* const* d_in, const int* in_sizes, int n_in,
                              void* d_out, int out_size) {
    const float* left  = (const float*)d_in[0];
    const float* right = (const float*)d_in[1];
    float* out = (float*)d_out;

    dim3 grid(WW / TJ, HH, BB);
    cost_volume_kernel<<<grid, THREADS>>>(left, right, out);
}

// round 8
// speedup vs baseline: 1.9413x; 1.0472x over previous
#include <cuda_runtime.h>
#include <cuda_fp16.h>
#include <cstdint>

#define BB 8
#define CC 128
#define HH 160
#define WW 512
#define DMAX 64
#define TJ 64
#define THREADS 128

#define SJ2 136           // sA row stride in half2 units (128 window cols + 8 pad)
#define SJB2 72           // sB row stride in half2 units (64 cols + 8 pad)
#define ASZ (16 * SJ2)    // 2176
#define BSZ (16 * SJB2)   // 1152
#define A0o 0
#define A1o ASZ
#define B0o (2 * ASZ)
#define B1o (2 * ASZ + BSZ)
#define SM_UINTS (2 * ASZ + 2 * BSZ)   // 6656 uints = 26624 B
#define SOUT_STRIDE 68                 // 64*68*4 = 17408 B, aliases buffers

__device__ __forceinline__ void mma_f16(float* d, const uint32_t* a, const uint32_t* b) {
    asm volatile(
        "mma.sync.aligned.m16n8k16.row.col.f32.f16.f16.f32 "
        "{%0,%1,%2,%3}, {%4,%5,%6,%7}, {%8,%9}, {%0,%1,%2,%3};"
        : "+f"(d[0]), "+f"(d[1]), "+f"(d[2]), "+f"(d[3])
        : "r"(a[0]), "r"(a[1]), "r"(a[2]), "r"(a[3]), "r"(b[0]), "r"(b[1]));
}
__device__ __forceinline__ uint32_t pack2(float lo, float hi) {
    const __half2 h = __floats2half2_rn(lo, hi);
    return *reinterpret_cast<const uint32_t*>(&h);
}

__global__ __launch_bounds__(THREADS, 4)
void cost_volume_kernel(const float* __restrict__ left,
                        const float* __restrict__ right,
                        float* __restrict__ out) {
    __shared__ uint32_t sm[SM_UINTS];

    const int tid = threadIdx.x;
    const int wid = tid >> 5;
    const int lid = tid & 31;
    const int gid = lid >> 2;       // 0..7
    const int tig = lid & 3;        // 0..3
    const int j0  = blockIdx.x * TJ;
    const int h   = blockIdx.y;
    const int b   = blockIdx.z;

    const size_t plane = (size_t)HH * WW;
    const float* Lbase = left  + ((size_t)b * CC * HH + h) * WW;
    const float* Rbase = right + ((size_t)b * CC * HH + h) * WW;

    // warp tile: warp w -> window rows k [w*32, +32), all jj [0,64)
    const int kw = wid * 32;

    // staging map: c2s = channel pair (16), gl = lane-in-group (8)
    const int c2s = tid >> 3;
    const int gl  = tid & 7;

    float acc[2][8][4];
    #pragma unroll
    for (int mt = 0; mt < 2; mt++)
        #pragma unroll
        for (int nt = 0; nt < 8; nt++)
            #pragma unroll
            for (int r = 0; r < 4; r++) acc[mt][nt][r] = 0.0f;

    for (int chunk = 0; chunk < 4; chunk++) {
        const int buf = chunk & 1;
        __syncthreads();   // prior compute on this buffer finished

        // ---- stage A: R window [c2][k 0..127], k -> gj = j0-64+k ----
        {
            const int ch = chunk * 32 + 2 * c2s;
            const float* R0 = Rbase + (size_t)ch * plane;
            const float* R1 = R0 + plane;
            uint32_t* Ab = sm + (buf ? A1o : A0o) + c2s * SJ2;
            #pragma unroll
            for (int i = 0; i < 4; i++) {
                const int q  = gl + 8 * i;           // col group 0..31
                const int gj = j0 - 64 + 4 * q;
                float4 e = make_float4(0.f, 0.f, 0.f, 0.f), o = e;
                if (gj >= 0) {
                    e = *reinterpret_cast<const float4*>(R0 + gj);
                    o = *reinterpret_cast<const float4*>(R1 + gj);
                }
                uint4 w;
                w.x = pack2(e.x, o.x); w.y = pack2(e.y, o.y);
                w.z = pack2(e.z, o.z); w.w = pack2(e.w, o.w);
                *reinterpret_cast<uint4*>(Ab + 4 * q) = w;
            }
            // ---- stage B: L tile [c2][jj 0..63] ----
            const float* L0 = Lbase + (size_t)ch * plane + j0;
            const float* L1 = L0 + plane;
            uint32_t* Bb = sm + (buf ? B1o : B0o) + c2s * SJB2;
            #pragma unroll
            for (int i = 0; i < 2; i++) {
                const int q = gl + 8 * i;            // col group 0..15
                const float4 e = *reinterpret_cast<const float4*>(L0 + 4 * q);
                const float4 o = *reinterpret_cast<const float4*>(L1 + 4 * q);
                uint4 w;
                w.x = pack2(e.x, o.x); w.y = pack2(e.y, o.y);
                w.z = pack2(e.z, o.z); w.w = pack2(e.w, o.w);
                *reinterpret_cast<uint4*>(Bb + 4 * q) = w;
            }
        }
        __syncthreads();

        // ---- compute: 2 k16 steps ----
        const uint32_t* Abase = sm + (buf ? A1o : A0o);
        const uint32_t* Bbase = sm + (buf ? B1o : B0o);
        #pragma unroll
        for (int s = 0; s < 2; s++) {
            const uint32_t* As  = Abase + (s * 8 + tig) * SJ2;
            const uint32_t* As4 = As + 4 * SJ2;
            const uint32_t* Bs  = Bbase + (s * 8 + tig) * SJB2;
            const uint32_t* Bs4 = Bs + 4 * SJB2;

            uint32_t af[2][4];
            #pragma unroll
            for (int mt = 0; mt < 2; mt++) {
                const int p = kw + mt * 16 + gid;
                af[mt][0] = As[p];   af[mt][1] = As[p + 8];
                af[mt][2] = As4[p];  af[mt][3] = As4[p + 8];
            }
            uint32_t bf[8][2];
            #pragma unroll
            for (int nt = 0; nt < 8; nt++) {
                const int jl = nt * 8 + gid;
                bf[nt][0] = Bs[jl];  bf[nt][1] = Bs4[jl];
            }
            #pragma unroll
            for (int mt = 0; mt < 2; mt++)
                #pragma unroll
                for (int nt = 0; nt < 8; nt++)
                    mma_f16(acc[mt][nt], af[mt], bf[nt]);
        }
    }

    // ---- epilogue: band extract -> smem alias -> coalesced store ----
    __syncthreads();
    {
        const float inv = 1.0f / (float)CC;
        float* sOut = reinterpret_cast<float*>(sm);
        #pragma unroll
        for (int mt = 0; mt < 2; mt++) {
            const int k0t = kw + mt * 16 + gid;
            #pragma unroll
            for (int nt = 0; nt < 8; nt++) {
                const int jj0t = nt * 8 + 2 * tig;
                #pragma unroll
                for (int r = 0; r < 4; r++) {
                    const int kk = k0t + ((r >= 2) ? 8 : 0);
                    const int jx = jj0t + (r & 1);
                    const int d  = jx + 64 - kk;
                    if (d >= 0 && d < 64) {
                        const int j = j0 + jx;
                        sOut[d * SOUT_STRIDE + jx] = (j >= d) ? acc[mt][nt][r] * inv : 0.0f;
                    }
                }
            }
        }
    }
    __syncthreads();
    {
        const float* sOut = reinterpret_cast<const float*>(sm);
        float* obase = out + ((size_t)b * DMAX * HH + h) * WW + j0;
        #pragma unroll
        for (int it = 0; it < 8; it++) {
            const int idx = it * THREADS + tid;   // 1024 float4 slots
            const int d  = idx >> 4;
            const int qq = idx & 15;
            const float4 v = *reinterpret_cast<const float4*>(sOut + d * SOUT_STRIDE + 4 * qq);
            *reinterpret_cast<float4*>(obase + (size_t)d * plane + 4 * qq) = v;
        }
    }
}

extern "C" void kernel_launch(void* const* d_in, const int* in_sizes, int n_in,
                              void* d_out, int out_size) {
    const float* left  = (const float*)d_in[0];
    const float* right = (const float*)d_in[1];
    float* out = (float*)d_out;

    dim3 grid(WW / TJ, HH, BB);
    cost_volume_kernel<<<grid, THREADS>>>(left, right, out);
}

// round 9
// speedup vs baseline: 2.0959x; 1.0797x over previous
#include <cuda_runtime.h>
#include <cuda_fp16.h>
#include <cstdint>

#define BB 8
#define CC 128
#define HH 160
#define WW 512
#define DMAX 64
#define TJ 64
#define THREADS 128

// f32 staging (single buffer)
#define OFF_FA 0
#define OFF_FB 16384            // A: 32ch x 128 cols x 4B
#define OFF_HA 24576            // B: 32ch x 64 cols x 4B
#define SJ2 136                 // f16 A tile row stride (half2)
#define SJB2 72                 // f16 B tile row stride (half2)
#define OFF_HB (OFF_HA + 16 * SJ2 * 4)       // 33280
#define SM_BYTES (OFF_HB + 16 * SJB2 * 4)    // 37888
#define SOUT_STRIDE 68          // 64*68*4 = 17408 B, aliases staging

__device__ __forceinline__ void mma_f16(float* d, const uint32_t* a, const uint32_t* b) {
    asm volatile(
        "mma.sync.aligned.m16n8k16.row.col.f32.f16.f16.f32 "
        "{%0,%1,%2,%3}, {%4,%5,%6,%7}, {%8,%9}, {%0,%1,%2,%3};"
        : "+f"(d[0]), "+f"(d[1]), "+f"(d[2]), "+f"(d[3])
        : "r"(a[0]), "r"(a[1]), "r"(a[2]), "r"(a[3]), "r"(b[0]), "r"(b[1]));
}
__device__ __forceinline__ uint32_t pack2(float lo, float hi) {
    const __half2 h = __floats2half2_rn(lo, hi);
    return *reinterpret_cast<const uint32_t*>(&h);
}
__device__ __forceinline__ void cpa16(uint32_t dst, const float* src) {
    asm volatile("cp.async.cg.shared.global [%0], [%1], 16;" :: "r"(dst), "l"(src));
}

__global__ __launch_bounds__(THREADS, 4)
void cost_volume_kernel(const float* __restrict__ left,
                        const float* __restrict__ right,
                        float* __restrict__ out) {
    extern __shared__ char smem[];
    const uint32_t sbase = (uint32_t)__cvta_generic_to_shared(smem);

    const int tid = threadIdx.x;
    const int wid = tid >> 5;
    const int lid = tid & 31;
    const int gid = lid >> 2;
    const int tig = lid & 3;
    const int j0  = blockIdx.x * TJ;
    const int h   = blockIdx.y;
    const int b   = blockIdx.z;

    const size_t plane = (size_t)HH * WW;
    const float* Lbase = left  + ((size_t)b * CC * HH + h) * WW;
    const float* Rbase = right + ((size_t)b * CC * HH + h) * WW;

    const int kw = wid * 32;    // warp's 32 window rows

    // ---- async stage: raw f32 chunk (32 channels) into fA/fB ----
    auto cp_stage = [&](int chunk) {
        const int ch0 = chunk * 32;
        #pragma unroll
        for (int i = 0; i < 8; i++) {           // A: 1024 x 16B granules
            const int g = tid + 128 * i;
            const int row = g >> 5, c16 = g & 31;
            int gj = j0 - 64 + c16 * 4;
            if (gj < 0) gj = 0;                 // feeds only masked j<d outputs
            cpa16(sbase + OFF_FA + row * 512 + c16 * 16,
                  Rbase + (size_t)(ch0 + row) * plane + gj);
        }
        #pragma unroll
        for (int i = 0; i < 4; i++) {           // B: 512 x 16B granules
            const int g = tid + 128 * i;
            const int row = g >> 4, c16 = g & 15;
            cpa16(sbase + OFF_FB + row * 256 + c16 * 16,
                  Lbase + (size_t)(ch0 + row) * plane + j0 + c16 * 4);
        }
        asm volatile("cp.async.commit_group;" ::: "memory");
    };

    float acc[2][8][4];
    #pragma unroll
    for (int mt = 0; mt < 2; mt++)
        #pragma unroll
        for (int nt = 0; nt < 8; nt++)
            #pragma unroll
            for (int r = 0; r < 4; r++) acc[mt][nt][r] = 0.0f;

    cp_stage(0);

    for (int c = 0; c < 4; c++) {
        asm volatile("cp.async.wait_group 0;" ::: "memory");
        __syncthreads();      // fA/fB ready; all warps done with hA/hB of prev chunk

        // ---- convert pass: f32 stage -> packed half2 tiles ----
        {
            const float* fA = reinterpret_cast<const float*>(smem + OFF_FA);
            const float* fB = reinterpret_cast<const float*>(smem + OFF_FB);
            uint32_t* hA = reinterpret_cast<uint32_t*>(smem + OFF_HA);
            uint32_t* hB = reinterpret_cast<uint32_t*>(smem + OFF_HB);
            #pragma unroll
            for (int i = 0; i < 4; i++) {       // A: 512 uint4 tasks
                const int g = tid + 128 * i;
                const int c2 = g >> 5, q4 = g & 31;
                const float4 e = *reinterpret_cast<const float4*>(fA + (2 * c2) * 128 + q4 * 4);
                const float4 o = *reinterpret_cast<const float4*>(fA + (2 * c2 + 1) * 128 + q4 * 4);
                uint4 w;
                w.x = pack2(e.x, o.x); w.y = pack2(e.y, o.y);
                w.z = pack2(e.z, o.z); w.w = pack2(e.w, o.w);
                *reinterpret_cast<uint4*>(hA + c2 * SJ2 + q4 * 4) = w;
            }
            #pragma unroll
            for (int i = 0; i < 2; i++) {       // B: 256 uint4 tasks
                const int g = tid + 128 * i;
                const int c2 = g >> 4, q4 = g & 15;
                const float4 e = *reinterpret_cast<const float4*>(fB + (2 * c2) * 64 + q4 * 4);
                const float4 o = *reinterpret_cast<const float4*>(fB + (2 * c2 + 1) * 64 + q4 * 4);
                uint4 w;
                w.x = pack2(e.x, o.x); w.y = pack2(e.y, o.y);
                w.z = pack2(e.z, o.z); w.w = pack2(e.w, o.w);
                *reinterpret_cast<uint4*>(hB + c2 * SJB2 + q4 * 4) = w;
            }
        }
        __syncthreads();      // f32 stage free, f16 tiles visible

        if (c < 3) cp_stage(c + 1);   // next chunk's DMA flies during compute

        // ---- compute: 2 k16 steps of mma.sync f16 ----
        {
            const uint32_t* Abase = reinterpret_cast<const uint32_t*>(smem + OFF_HA);
            const uint32_t* Bbase = reinterpret_cast<const uint32_t*>(smem + OFF_HB);
            #pragma unroll
            for (int s = 0; s < 2; s++) {
                const uint32_t* As  = Abase + (s * 8 + tig) * SJ2;
                const uint32_t* As4 = As + 4 * SJ2;
                const uint32_t* Bs  = Bbase + (s * 8 + tig) * SJB2;
                const uint32_t* Bs4 = Bs + 4 * SJB2;

                uint32_t af[2][4];
                #pragma unroll
                for (int mt = 0; mt < 2; mt++) {
                    const int p = kw + mt * 16 + gid;
                    af[mt][0] = As[p];   af[mt][1] = As[p + 8];
                    af[mt][2] = As4[p];  af[mt][3] = As4[p + 8];
                }
                uint32_t bf[8][2];
                #pragma unroll
                for (int nt = 0; nt < 8; nt++) {
                    const int jl = nt * 8 + gid;
                    bf[nt][0] = Bs[jl];  bf[nt][1] = Bs4[jl];
                }
                #pragma unroll
                for (int mt = 0; mt < 2; mt++)
                    #pragma unroll
                    for (int nt = 0; nt < 8; nt++)
                        mma_f16(acc[mt][nt], af[mt], bf[nt]);
            }
        }
    }

    // ---- epilogue: band extract -> smem alias -> coalesced store ----
    __syncthreads();
    {
        const float inv = 1.0f / (float)CC;
        float* sOut = reinterpret_cast<float*>(smem);
        #pragma unroll
        for (int mt = 0; mt < 2; mt++) {
            const int k0t = kw + mt * 16 + gid;
            #pragma unroll
            for (int nt = 0; nt < 8; nt++) {
                const int jj0t = nt * 8 + 2 * tig;
                #pragma unroll
                for (int r = 0; r < 4; r++) {
                    const int kk = k0t + ((r >= 2) ? 8 : 0);
                    const int jx = jj0t + (r & 1);
                    const int d  = jx + 64 - kk;
                    if (d >= 0 && d < 64) {
                        const int j = j0 + jx;
                        sOut[d * SOUT_STRIDE + jx] = (j >= d) ? acc[mt][nt][r] * inv : 0.0f;
                    }
                }
            }
        }
    }
    __syncthreads();
    {
        const float* sOut = reinterpret_cast<const float*>(smem);
        float* obase = out + ((size_t)b * DMAX * HH + h) * WW + j0;
        #pragma unroll
        for (int it = 0; it < 8; it++) {
            const int idx = it * THREADS + tid;
            const int d  = idx >> 4;
            const int qq = idx & 15;
            const float4 v = *reinterpret_cast<const float4*>(sOut + d * SOUT_STRIDE + 4 * qq);
            *reinterpret_cast<float4*>(obase + (size_t)d * plane + 4 * qq) = v;
        }
    }
}

extern "C" void kernel_launch(void* const* d_in, const int* in_sizes, int n_in,
                              void* d_out, int out_size) {
    const float* left  = (const float*)d_in[0];
    const float* right = (const float*)d_in[1];
    float* out = (float*)d_out;

    cudaFuncSetAttribute(cost_volume_kernel,
                         cudaFuncAttributeMaxDynamicSharedMemorySize, SM_BYTES);

    dim3 grid(WW / TJ, HH, BB);
    cost_volume_kernel<<<grid, THREADS, SM_BYTES>>>(left, right, out);
}

// round 10
// speedup vs baseline: 2.3004x; 1.0976x over previous
#include <cuda_runtime.h>
#include <cuda_fp16.h>
#include <cstdint>

#define BB 8
#define CC 128
#define HH 160
#define WW 512
#define DMAX 64
#define TJ 64
#define THREADS 128

// 16-channel chunks, 3-deep f32 staging ring
#define STAGE_BYTES 12288        // A: 16x128x4 = 8192, B: 16x64x4 = 4096
#define OFF_FB_IN_STAGE 8192
#define OFF_H  (3 * STAGE_BYTES) // 36864
#define SJ2 136                  // f16 A tile row stride (half2 units)
#define SJB2 72                  // f16 B tile row stride (half2 units)
#define OFF_HA OFF_H
#define OFF_HB (OFF_H + 8 * SJ2 * 4)         // 41216
#define SM_BYTES (OFF_HB + 8 * SJB2 * 4)     // 43520
#define SOUT_STRIDE 68           // 64*68*4 = 17408 B, aliases staging ring

__device__ __forceinline__ void mma_f16(float* d, const uint32_t* a, const uint32_t* b) {
    asm volatile(
        "mma.sync.aligned.m16n8k16.row.col.f32.f16.f16.f32 "
        "{%0,%1,%2,%3}, {%4,%5,%6,%7}, {%8,%9}, {%0,%1,%2,%3};"
        : "+f"(d[0]), "+f"(d[1]), "+f"(d[2]), "+f"(d[3])
        : "r"(a[0]), "r"(a[1]), "r"(a[2]), "r"(a[3]), "r"(b[0]), "r"(b[1]));
}
__device__ __forceinline__ uint32_t pack2(float lo, float hi) {
    const __half2 h = __floats2half2_rn(lo, hi);
    return *reinterpret_cast<const uint32_t*>(&h);
}
__device__ __forceinline__ void cpa16(uint32_t dst, const float* src) {
    asm volatile("cp.async.cg.shared.global [%0], [%1], 16;" :: "r"(dst), "l"(src));
}

__global__ __launch_bounds__(THREADS, 4)
void cost_volume_kernel(const float* __restrict__ left,
                        const float* __restrict__ right,
                        float* __restrict__ out) {
    extern __shared__ char smem[];
    const uint32_t sbase = (uint32_t)__cvta_generic_to_shared(smem);

    const int tid = threadIdx.x;
    const int wid = tid >> 5;
    const int lid = tid & 31;
    const int gid = lid >> 2;
    const int tig = lid & 3;
    const int j0  = blockIdx.x * TJ;
    const int h   = blockIdx.y;
    const int b   = blockIdx.z;

    const size_t plane = (size_t)HH * WW;
    const float* Lbase = left  + ((size_t)b * CC * HH + h) * WW;
    const float* Rbase = right + ((size_t)b * CC * HH + h) * WW;

    const int kw = wid * 32;    // warp's 32 window rows

    // ---- async stage: 16-channel chunk into ring slot `buf` ----
    auto cp_stage = [&](int chunk, int buf) {
        const int ch0 = chunk * 16;
        const uint32_t base = sbase + buf * STAGE_BYTES;
        #pragma unroll
        for (int i = 0; i < 4; i++) {            // A: 512 granules of 16B
            const int g = tid + 128 * i;
            const int row = g >> 5, c16 = g & 31;
            int gj = j0 - 64 + c16 * 4;
            if (gj < 0) gj = 0;                  // feeds only masked j<d outputs
            cpa16(base + row * 512 + c16 * 16,
                  Rbase + (size_t)(ch0 + row) * plane + gj);
        }
        #pragma unroll
        for (int i = 0; i < 2; i++) {            // B: 256 granules of 16B
            const int g = tid + 128 * i;
            const int row = g >> 4, c16 = g & 15;
            cpa16(base + OFF_FB_IN_STAGE + row * 256 + c16 * 16,
                  Lbase + (size_t)(ch0 + row) * plane + j0 + c16 * 4);
        }
        asm volatile("cp.async.commit_group;" ::: "memory");
    };

    float acc[2][8][4];
    #pragma unroll
    for (int mt = 0; mt < 2; mt++)
        #pragma unroll
        for (int nt = 0; nt < 8; nt++)
            #pragma unroll
            for (int r = 0; r < 4; r++) acc[mt][nt][r] = 0.0f;

    cp_stage(0, 0); cp_stage(1, 1); cp_stage(2, 2);

    int buf = 0;
    for (int c = 0; c < 8; c++) {
        // chunk c complete when at most min(2, 7-c) groups remain pending
        if (c < 6)       asm volatile("cp.async.wait_group 2;" ::: "memory");
        else if (c == 6) asm volatile("cp.async.wait_group 1;" ::: "memory");
        else             asm volatile("cp.async.wait_group 0;" ::: "memory");
        __syncthreads();   // stage(c) ready; all warps done with f16 tiles of c-1

        // ---- convert: f32 stage -> packed half2 tiles ----
        {
            const float* fA = reinterpret_cast<const float*>(smem + buf * STAGE_BYTES);
            const float* fB = reinterpret_cast<const float*>(smem + buf * STAGE_BYTES + OFF_FB_IN_STAGE);
            uint32_t* hA = reinterpret_cast<uint32_t*>(smem + OFF_HA);
            uint32_t* hB = reinterpret_cast<uint32_t*>(smem + OFF_HB);
            #pragma unroll
            for (int i = 0; i < 2; i++) {        // A: 256 uint4 tasks
                const int g = tid + 128 * i;
                const int c2 = g >> 5, q4 = g & 31;
                const float4 e = *reinterpret_cast<const float4*>(fA + (2 * c2) * 128 + q4 * 4);
                const float4 o = *reinterpret_cast<const float4*>(fA + (2 * c2 + 1) * 128 + q4 * 4);
                uint4 w;
                w.x = pack2(e.x, o.x); w.y = pack2(e.y, o.y);
                w.z = pack2(e.z, o.z); w.w = pack2(e.w, o.w);
                *reinterpret_cast<uint4*>(hA + c2 * SJ2 + q4 * 4) = w;
            }
            {                                     // B: 128 uint4 tasks
                const int c2 = tid >> 4, q4 = tid & 15;
                const float4 e = *reinterpret_cast<const float4*>(fB + (2 * c2) * 64 + q4 * 4);
                const float4 o = *reinterpret_cast<const float4*>(fB + (2 * c2 + 1) * 64 + q4 * 4);
                uint4 w;
                w.x = pack2(e.x, o.x); w.y = pack2(e.y, o.y);
                w.z = pack2(e.z, o.z); w.w = pack2(e.w, o.w);
                *reinterpret_cast<uint4*>(hB + c2 * SJB2 + q4 * 4) = w;
            }
        }
        __syncthreads();   // stage slot free, f16 tiles visible

        if (c + 3 < 8) cp_stage(c + 3, buf);   // refill this slot; 3 groups in flight

        // ---- compute: one k16 step ----
        {
            const uint32_t* As  = reinterpret_cast<const uint32_t*>(smem + OFF_HA) + tig * SJ2;
            const uint32_t* As4 = As + 4 * SJ2;
            const uint32_t* Bs  = reinterpret_cast<const uint32_t*>(smem + OFF_HB) + tig * SJB2;
            const uint32_t* Bs4 = Bs + 4 * SJB2;

            uint32_t af[2][4];
            #pragma unroll
            for (int mt = 0; mt < 2; mt++) {
                const int p = kw + mt * 16 + gid;
                af[mt][0] = As[p];   af[mt][1] = As[p + 8];
                af[mt][2] = As4[p];  af[mt][3] = As4[p + 8];
            }
            uint32_t bf[8][2];
            #pragma unroll
            for (int nt = 0; nt < 8; nt++) {
                const int jl = nt * 8 + gid;
                bf[nt][0] = Bs[jl];  bf[nt][1] = Bs4[jl];
            }
            #pragma unroll
            for (int mt = 0; mt < 2; mt++)
                #pragma unroll
                for (int nt = 0; nt < 8; nt++)
                    mma_f16(acc[mt][nt], af[mt], bf[nt]);
        }

        buf = (buf == 2) ? 0 : buf + 1;
    }

    // ---- epilogue: band extract -> smem alias -> coalesced store ----
    __syncthreads();
    {
        const float inv = 1.0f / (float)CC;
        float* sOut = reinterpret_cast<float*>(smem);
        #pragma unroll
        for (int mt = 0; mt < 2; mt++) {
            const int k0t = kw + mt * 16 + gid;
            #pragma unroll
            for (int nt = 0; nt < 8; nt++) {
                const int jj0t = nt * 8 + 2 * tig;
                #pragma unroll
                for (int r = 0; r < 4; r++) {
                    const int kk = k0t + ((r >= 2) ? 8 : 0);
                    const int jx = jj0t + (r & 1);
                    const int d  = jx + 64 - kk;
                    if (d >= 0 && d < 64) {
                        const int j = j0 + jx;
                        sOut[d * SOUT_STRIDE + jx] = (j >= d) ? acc[mt][nt][r] * inv : 0.0f;
                    }
                }
            }
        }
    }
    __syncthreads();
    {
        const float* sOut = reinterpret_cast<const float*>(smem);
        float* obase = out + ((size_t)b * DMAX * HH + h) * WW + j0;
        #pragma unroll
        for (int it = 0; it < 8; it++) {
            const int idx = it * THREADS + tid;
            const int d  = idx >> 4;
            const int qq = idx & 15;
            const float4 v = *reinterpret_cast<const float4*>(sOut + d * SOUT_STRIDE + 4 * qq);
            *reinterpret_cast<float4*>(obase + (size_t)d * plane + 4 * qq) = v;
        }
    }
}

extern "C" void kernel_launch(void* const* d_in, const int* in_sizes, int n_in,
                              void* d_out, int out_size) {
    const float* left  = (const float*)d_in[0];
    const float* right = (const float*)d_in[1];
    float* out = (float*)d_out;

    cudaFuncSetAttribute(cost_volume_kernel,
                         cudaFuncAttributeMaxDynamicSharedMemorySize, SM_BYTES);

    dim3 grid(WW / TJ, HH, BB);
    cost_volume_kernel<<<grid, THREADS, SM_BYTES>>>(left, right, out);
}

// round 11
// speedup vs baseline: 2.3559x; 1.0241x over previous
#include <cuda_runtime.h>
#include <cuda_fp16.h>
#include <cstdint>

#define BB 8
#define CC 128
#define HH 160
#define WW 512
#define DMAX 64
#define TJ 64
#define THREADS 128

// 16-channel chunks, 4-deep f32 staging ring
#define STAGE_BYTES 12288        // A: 16x128x4 = 8192, B: 16x64x4 = 4096
#define OFF_FB_IN_STAGE 8192
#define NRING 4
#define OFF_H  (NRING * STAGE_BYTES)         // 49152
#define SJ2 136                  // f16 A tile row stride (half2 units)
#define SJB2 72                  // f16 B tile row stride (half2 units)
#define OFF_HA OFF_H
#define OFF_HB (OFF_H + 8 * SJ2 * 4)         // 53504
#define SM_BYTES (OFF_HB + 8 * SJB2 * 4)     // 55808
#define SOUT_STRIDE 68           // 64*68*4 = 17408 B, aliases staging ring

__device__ __forceinline__ void mma_f16(float* d, const uint32_t* a, const uint32_t* b) {
    asm volatile(
        "mma.sync.aligned.m16n8k16.row.col.f32.f16.f16.f32 "
        "{%0,%1,%2,%3}, {%4,%5,%6,%7}, {%8,%9}, {%0,%1,%2,%3};"
        : "+f"(d[0]), "+f"(d[1]), "+f"(d[2]), "+f"(d[3])
        : "r"(a[0]), "r"(a[1]), "r"(a[2]), "r"(a[3]), "r"(b[0]), "r"(b[1]));
}
__device__ __forceinline__ uint32_t pack2(float lo, float hi) {
    const __half2 h = __floats2half2_rn(lo, hi);
    return *reinterpret_cast<const uint32_t*>(&h);
}
__device__ __forceinline__ void cpa16(uint32_t dst, const float* src) {
    asm volatile("cp.async.cg.shared.global [%0], [%1], 16;" :: "r"(dst), "l"(src));
}

__global__ __launch_bounds__(THREADS, 4)
void cost_volume_kernel(const float* __restrict__ left,
                        const float* __restrict__ right,
                        float* __restrict__ out) {
    extern __shared__ char smem[];
    const uint32_t sbase = (uint32_t)__cvta_generic_to_shared(smem);

    const int tid = threadIdx.x;
    const int wid = tid >> 5;
    const int lid = tid & 31;
    const int gid = lid >> 2;
    const int tig = lid & 3;
    const int j0  = blockIdx.x * TJ;
    const int h   = blockIdx.y;
    const int b   = blockIdx.z;

    const size_t plane = (size_t)HH * WW;
    const float* Lbase = left  + ((size_t)b * CC * HH + h) * WW;
    const float* Rbase = right + ((size_t)b * CC * HH + h) * WW;

    const int kw = wid * 32;    // warp's 32 window rows

    // ---- async stage: 16-channel chunk into ring slot `buf` ----
    auto cp_stage = [&](int chunk, int buf) {
        const int ch0 = chunk * 16;
        const uint32_t base = sbase + buf * STAGE_BYTES;
        #pragma unroll
        for (int i = 0; i < 4; i++) {            // A: 512 granules of 16B
            const int g = tid + 128 * i;
            const int row = g >> 5, c16 = g & 31;
            int gj = j0 - 64 + c16 * 4;
            if (gj < 0) gj = 0;                  // feeds only masked j<d outputs
            cpa16(base + row * 512 + c16 * 16,
                  Rbase + (size_t)(ch0 + row) * plane + gj);
        }
        #pragma unroll
        for (int i = 0; i < 2; i++) {            // B: 256 granules of 16B
            const int g = tid + 128 * i;
            const int row = g >> 4, c16 = g & 15;
            cpa16(base + OFF_FB_IN_STAGE + row * 256 + c16 * 16,
                  Lbase + (size_t)(ch0 + row) * plane + j0 + c16 * 4);
        }
        asm volatile("cp.async.commit_group;" ::: "memory");
    };

    float acc[2][8][4];
    #pragma unroll
    for (int mt = 0; mt < 2; mt++)
        #pragma unroll
        for (int nt = 0; nt < 8; nt++)
            #pragma unroll
            for (int r = 0; r < 4; r++) acc[mt][nt][r] = 0.0f;

    cp_stage(0, 0); cp_stage(1, 1); cp_stage(2, 2); cp_stage(3, 3);

    int buf = 0;
    for (int c = 0; c < 8; c++) {
        // chunk c complete when at most min(3, 7-c) groups remain pending
        if (c < 5)       asm volatile("cp.async.wait_group 3;" ::: "memory");
        else if (c == 5) asm volatile("cp.async.wait_group 2;" ::: "memory");
        else if (c == 6) asm volatile("cp.async.wait_group 1;" ::: "memory");
        else             asm volatile("cp.async.wait_group 0;" ::: "memory");
        __syncthreads();   // stage(c) ready; all warps done with f16 tiles of c-1

        // ---- convert: f32 stage -> packed half2 tiles ----
        {
            const float* fA = reinterpret_cast<const float*>(smem + buf * STAGE_BYTES);
            const float* fB = reinterpret_cast<const float*>(smem + buf * STAGE_BYTES + OFF_FB_IN_STAGE);
            uint32_t* hA = reinterpret_cast<uint32_t*>(smem + OFF_HA);
            uint32_t* hB = reinterpret_cast<uint32_t*>(smem + OFF_HB);
            #pragma unroll
            for (int i = 0; i < 2; i++) {        // A: 256 uint4 tasks
                const int g = tid + 128 * i;
                const int c2 = g >> 5, q4 = g & 31;
                const float4 e = *reinterpret_cast<const float4*>(fA + (2 * c2) * 128 + q4 * 4);
                const float4 o = *reinterpret_cast<const float4*>(fA + (2 * c2 + 1) * 128 + q4 * 4);
                uint4 w;
                w.x = pack2(e.x, o.x); w.y = pack2(e.y, o.y);
                w.z = pack2(e.z, o.z); w.w = pack2(e.w, o.w);
                *reinterpret_cast<uint4*>(hA + c2 * SJ2 + q4 * 4) = w;
            }
            {                                     // B: 128 uint4 tasks
                const int c2 = tid >> 4, q4 = tid & 15;
                const float4 e = *reinterpret_cast<const float4*>(fB + (2 * c2) * 64 + q4 * 4);
                const float4 o = *reinterpret_cast<const float4*>(fB + (2 * c2 + 1) * 64 + q4 * 4);
                uint4 w;
                w.x = pack2(e.x, o.x); w.y = pack2(e.y, o.y);
                w.z = pack2(e.z, o.z); w.w = pack2(e.w, o.w);
                *reinterpret_cast<uint4*>(hB + c2 * SJB2 + q4 * 4) = w;
            }
        }
        __syncthreads();   // stage slot free, f16 tiles visible

        if (c + NRING < 8) cp_stage(c + NRING, buf);   // refill; 4 groups in flight

        // ---- compute: one k16 step ----
        {
            const uint32_t* As  = reinterpret_cast<const uint32_t*>(smem + OFF_HA) + tig * SJ2;
            const uint32_t* As4 = As + 4 * SJ2;
            const uint32_t* Bs  = reinterpret_cast<const uint32_t*>(smem + OFF_HB) + tig * SJB2;
            const uint32_t* Bs4 = Bs + 4 * SJB2;

            uint32_t af[2][4];
            #pragma unroll
            for (int mt = 0; mt < 2; mt++) {
                const int p = kw + mt * 16 + gid;
                af[mt][0] = As[p];   af[mt][1] = As[p + 8];
                af[mt][2] = As4[p];  af[mt][3] = As4[p + 8];
            }
            uint32_t bf[8][2];
            #pragma unroll
            for (int nt = 0; nt < 8; nt++) {
                const int jl = nt * 8 + gid;
                bf[nt][0] = Bs[jl];  bf[nt][1] = Bs4[jl];
            }
            #pragma unroll
            for (int mt = 0; mt < 2; mt++)
                #pragma unroll
                for (int nt = 0; nt < 8; nt++)
                    mma_f16(acc[mt][nt], af[mt], bf[nt]);
        }

        buf = (buf == NRING - 1) ? 0 : buf + 1;
    }

    // ---- epilogue: band extract -> smem alias -> coalesced store ----
    __syncthreads();
    {
        const float inv = 1.0f / (float)CC;
        float* sOut = reinterpret_cast<float*>(smem);
        #pragma unroll
        for (int mt = 0; mt < 2; mt++) {
            const int k0t = kw + mt * 16 + gid;
            #pragma unroll
            for (int nt = 0; nt < 8; nt++) {
                const int jj0t = nt * 8 + 2 * tig;
                #pragma unroll
                for (int r = 0; r < 4; r++) {
                    const int kk = k0t + ((r >= 2) ? 8 : 0);
                    const int jx = jj0t + (r & 1);
                    const int d  = jx + 64 - kk;
                    if (d >= 0 && d < 64) {
                        const int j = j0 + jx;
                        sOut[d * SOUT_STRIDE + jx] = (j >= d) ? acc[mt][nt][r] * inv : 0.0f;
                    }
                }
            }
        }
    }
    __syncthreads();
    {
        const float* sOut = reinterpret_cast<const float*>(smem);
        float* obase = out + ((size_t)b * DMAX * HH + h) * WW + j0;
        #pragma unroll
        for (int it = 0; it < 8; it++) {
            const int idx = it * THREADS + tid;
            const int d  = idx >> 4;
            const int qq = idx & 15;
            const float4 v = *reinterpret_cast<const float4*>(sOut + d * SOUT_STRIDE + 4 * qq);
            *reinterpret_cast<float4*>(obase + (size_t)d * plane + 4 * qq) = v;
        }
    }
}

extern "C" void kernel_launch(void* const* d_in, const int* in_sizes, int n_in,
                              void* d_out, int out_size) {
    const float* left  = (const float*)d_in[0];
    const float* right = (const float*)d_in[1];
    float* out = (float*)d_out;

    cudaFuncSetAttribute(cost_volume_kernel,
                         cudaFuncAttributeMaxDynamicSharedMemorySize, SM_BYTES);

    dim3 grid(WW / TJ, HH, BB);
    cost_volume_kernel<<<grid, THREADS, SM_BYTES>>>(left, right, out);
}